// round 9
// baseline (speedup 1.0000x reference)
#include <cuda_runtime.h>

// Shapes: x (B=2, C=64, T=16, H=128, W=128) fp32; w (1, 2, 7, 7, 7) fp32.
// out = sigmoid(conv3d(concat(max_c(x), mean_c(x)), w, pad=3)) * x
#define CC   64
#define TT   16
#define HH   128
#define WW   128
#define HWSZ (HH * WW)           // 16384
#define THW  (TT * HWSZ)         // 262144
#define BB   2

// Scratch: maps (B,2,T,H,W) = 4 MB, attn (B,T,H,W) = 2 MB
__device__ __align__(16) float g_maps[BB * 2 * THW];
__device__ __align__(16) float g_attn[BB * THW];

// ---------------------------------------------------------------------------
// Kernel 1: channel max + mean.  One thread = one float4 spatial position,
// 64 coalesced strided float4 loads (stride 1 MB), MLP from unroll.
// ---------------------------------------------------------------------------
__global__ void reduce_kernel(const float* __restrict__ x) {
    int idx = blockIdx.x * blockDim.x + threadIdx.x;  // [0, B*THW/4)
    int b  = idx >> 16;                                // THW/4 = 65536
    int s4 = idx & 65535;

    const float4* x4 = (const float4*)x;
    int base = b * (CC * (THW / 4)) + s4;              // max 8388608, fits int

    float4 v = x4[base];
    float4 mx = v;
    float4 sm = v;
#pragma unroll 7
    for (int c = 1; c < CC; ++c) {
        float4 u = x4[base + c * (THW / 4)];
        mx.x = fmaxf(mx.x, u.x); mx.y = fmaxf(mx.y, u.y);
        mx.z = fmaxf(mx.z, u.z); mx.w = fmaxf(mx.w, u.w);
        sm.x += u.x; sm.y += u.y; sm.z += u.z; sm.w += u.w;
    }
    const float inv = 1.0f / 64.0f;
    float4 av = make_float4(sm.x * inv, sm.y * inv, sm.z * inv, sm.w * inv);

    float4* m4 = (float4*)g_maps;
    m4[(b * 2 + 0) * (THW / 4) + s4] = mx;
    m4[(b * 2 + 1) * (THW / 4) + s4] = av;
}

// ---------------------------------------------------------------------------
// Kernel 2: 7x7x7 conv over (B,2,T,H,W) maps + sigmoid -> g_attn.
// Block = (16,8) threads, output tile 64(w) x 16(h) at fixed (b,t).
// Each thread computes 4(w) x 2(h) outputs with a sliding register window
// in kh (rolling lo/hi rows), float4 LDS (conflict-free).
// Smem: weights (686 fl) + one t-slice 2ch x 22rows x stride72.
// ---------------------------------------------------------------------------
#define SSTR  72                 // smem row stride (floats), mult of 4
#define SCH   (22 * SSTR)        // per-channel smem slice (1584 floats)

__global__ void conv_kernel(const float* __restrict__ w) {
    __shared__ float s_w[688];
    __shared__ float s_in[2 * SCH];

    int tx  = threadIdx.x;               // 0..15
    int ty  = threadIdx.y;               // 0..7
    int tid = ty * 16 + tx;              // 0..127
    int w0  = blockIdx.x * 64;
    int h0  = blockIdx.y * 16;
    int b   = blockIdx.z >> 4;
    int t   = blockIdx.z & 15;

    for (int i = tid; i < 686; i += 128) s_w[i] = w[i];

    float a0[4] = {0.f, 0.f, 0.f, 0.f};
    float a1[4] = {0.f, 0.f, 0.f, 0.f};

    for (int kt = 0; kt < 7; ++kt) {
        int tin = t + kt - 3;
        if (tin < 0 || tin >= TT) continue;   // uniform per block (t uniform)

        __syncthreads();  // prior compute done before overwriting slice
        // Load slice: 2 ch x 22 rows x 70 cols, zero-padded at H/W borders
        const float* src = g_maps + ((b * 2) * TT + tin) * HWSZ;
        for (int i = tid; i < 2 * 22 * 70; i += 128) {
            int c  = i / 1540;
            int r  = i - c * 1540;
            int hh = r / 70;
            int ww = r - hh * 70;
            int gh = h0 - 3 + hh;
            int gw = w0 - 3 + ww;
            float val = 0.f;
            if ((unsigned)gh < (unsigned)HH && (unsigned)gw < (unsigned)WW)
                val = src[c * THW + gh * WW + gw];
            s_in[c * SCH + hh * SSTR + ww] = val;
        }
        __syncthreads();

#pragma unroll
        for (int c = 0; c < 2; ++c) {
            const float* basep = s_in + c * SCH + tx * 4;
            float lo[12], hi[12];
            {
                const float4* p = (const float4*)(basep + (ty * 2) * SSTR);
                float4 q0 = p[0], q1 = p[1], q2 = p[2];
                lo[0]=q0.x; lo[1]=q0.y; lo[2]=q0.z; lo[3]=q0.w;
                lo[4]=q1.x; lo[5]=q1.y; lo[6]=q1.z; lo[7]=q1.w;
                lo[8]=q2.x; lo[9]=q2.y; lo[10]=q2.z; lo[11]=q2.w;
                p = (const float4*)(basep + (ty * 2 + 1) * SSTR);
                q0 = p[0]; q1 = p[1]; q2 = p[2];
                hi[0]=q0.x; hi[1]=q0.y; hi[2]=q0.z; hi[3]=q0.w;
                hi[4]=q1.x; hi[5]=q1.y; hi[6]=q1.z; hi[7]=q1.w;
                hi[8]=q2.x; hi[9]=q2.y; hi[10]=q2.z; hi[11]=q2.w;
            }
#pragma unroll
            for (int kh = 0; kh < 7; ++kh) {
                if (kh > 0) {
#pragma unroll
                    for (int m = 0; m < 12; ++m) lo[m] = hi[m];
                    const float4* p =
                        (const float4*)(basep + (ty * 2 + kh + 1) * SSTR);
                    float4 q0 = p[0], q1 = p[1], q2 = p[2];
                    hi[0]=q0.x; hi[1]=q0.y; hi[2]=q0.z; hi[3]=q0.w;
                    hi[4]=q1.x; hi[5]=q1.y; hi[6]=q1.z; hi[7]=q1.w;
                    hi[8]=q2.x; hi[9]=q2.y; hi[10]=q2.z; hi[11]=q2.w;
                }
                const float* wp = s_w + c * 343 + kt * 49 + kh * 7;
#pragma unroll
                for (int kw = 0; kw < 7; ++kw) {
                    float wv = wp[kw];
#pragma unroll
                    for (int j = 0; j < 4; ++j) {
                        a0[j] = fmaf(wv, lo[kw + j], a0[j]);
                        a1[j] = fmaf(wv, hi[kw + j], a1[j]);
                    }
                }
            }
        }
    }

    // sigmoid + float4 store to g_attn
    int oh = h0 + ty * 2;
    float4 o0, o1;
    o0.x = 1.0f / (1.0f + __expf(-a0[0]));
    o0.y = 1.0f / (1.0f + __expf(-a0[1]));
    o0.z = 1.0f / (1.0f + __expf(-a0[2]));
    o0.w = 1.0f / (1.0f + __expf(-a0[3]));
    o1.x = 1.0f / (1.0f + __expf(-a1[0]));
    o1.y = 1.0f / (1.0f + __expf(-a1[1]));
    o1.z = 1.0f / (1.0f + __expf(-a1[2]));
    o1.w = 1.0f / (1.0f + __expf(-a1[3]));

    float4* att4 = (float4*)g_attn;
    int wq = blockIdx.x * 16 + tx;                        // w0/4 + tx
    int base = b * (THW / 4) + t * (HWSZ / 4) + oh * (WW / 4) + wq;
    att4[base]            = o0;
    att4[base + WW / 4]   = o1;
}

// ---------------------------------------------------------------------------
// Kernel 3: out = attn * x (broadcast over C). Pure streaming, float4.
// attn (4 MB total) stays L2-resident across the 64x reuse.
// ---------------------------------------------------------------------------
__global__ void mul_kernel(const float* __restrict__ x, float* __restrict__ out) {
    int idx = blockIdx.x * blockDim.x + threadIdx.x;   // float4 index
    int b  = idx >> 22;                                 // C*THW/4 = 2^22 per b
    int s4 = idx & 65535;                               // spatial f4 within ch

    float4 a = ((const float4*)g_attn)[b * 65536 + s4];
    float4 v = ((const float4*)x)[idx];
    float4 o = make_float4(v.x * a.x, v.y * a.y, v.z * a.z, v.w * a.w);
    ((float4*)out)[idx] = o;
}

// ---------------------------------------------------------------------------
extern "C" void kernel_launch(void* const* d_in, const int* in_sizes, int n_in,
                              void* d_out, int out_size) {
    const float* x = (const float*)d_in[0];   // 33554432 floats
    const float* w = (const float*)d_in[1];   // 686 floats
    float* out = (float*)d_out;

    // 1) channel max/mean: B*THW/4 = 131072 threads
    reduce_kernel<<<512, 256>>>(x);

    // 2) conv + sigmoid: tiles 64w x 16h, grid (W/64, H/16, B*T)
    dim3 cgrid(WW / 64, HH / 16, BB * TT);
    dim3 cblk(16, 8);
    conv_kernel<<<cgrid, cblk>>>(w);

    // 3) broadcast multiply: B*C*THW/4 = 8388608 threads
    mul_kernel<<<32768, 256>>>(x, out);
}

// round 10
// speedup vs baseline: 1.0243x; 1.0243x over previous
#include <cuda_runtime.h>

// Shapes: x (B=2, C=64, T=16, H=128, W=128) fp32; w (1, 2, 7, 7, 7) fp32.
// out = sigmoid(conv3d(concat(max_c(x), mean_c(x)), w, pad=3)) * x
#define CC   64
#define TT   16
#define HH   128
#define WW   128
#define HWSZ (HH * WW)           // 16384
#define THW  (TT * HWSZ)         // 262144
#define BB   2

// Scratch: maps (B,2,T,H,W) = 4 MB, attn (B,T,H,W) = 2 MB
__device__ __align__(16) float g_maps[BB * 2 * THW];
__device__ __align__(16) float g_attn[BB * THW];

// ---------------------------------------------------------------------------
// Kernel 1: channel max + mean.  One thread = one float4 spatial position,
// 64 coalesced strided float4 loads (stride 1 MB), MLP from unroll.
// ---------------------------------------------------------------------------
__global__ void reduce_kernel(const float* __restrict__ x) {
    int idx = blockIdx.x * blockDim.x + threadIdx.x;  // [0, B*THW/4)
    int b  = idx >> 16;                                // THW/4 = 65536
    int s4 = idx & 65535;

    const float4* x4 = (const float4*)x;
    int base = b * (CC * (THW / 4)) + s4;              // max 8388608, fits int

    float4 v = x4[base];
    float4 mx = v;
    float4 sm = v;
#pragma unroll 7
    for (int c = 1; c < CC; ++c) {
        float4 u = x4[base + c * (THW / 4)];
        mx.x = fmaxf(mx.x, u.x); mx.y = fmaxf(mx.y, u.y);
        mx.z = fmaxf(mx.z, u.z); mx.w = fmaxf(mx.w, u.w);
        sm.x += u.x; sm.y += u.y; sm.z += u.z; sm.w += u.w;
    }
    const float inv = 1.0f / 64.0f;
    float4 av = make_float4(sm.x * inv, sm.y * inv, sm.z * inv, sm.w * inv);

    float4* m4 = (float4*)g_maps;
    m4[(b * 2 + 0) * (THW / 4) + s4] = mx;
    m4[(b * 2 + 1) * (THW / 4) + s4] = av;
}

// ---------------------------------------------------------------------------
// Kernel 2: 7x7x7 conv over (B,2,T,H,W) maps + sigmoid -> g_attn.
// Block = (16,8) threads, output tile 64(w) x 16(h) at fixed (b,t).
// Each thread computes 4(w) x 2(h) outputs with a sliding register window
// in kh (rolling lo/hi rows), float4 LDS (conflict-free).
// Smem: weights (686 fl) + one t-slice 2ch x 22rows x stride72.
// ---------------------------------------------------------------------------
#define SSTR  72                 // smem row stride (floats), mult of 4
#define SCH   (22 * SSTR)        // per-channel smem slice (1584 floats)

__global__ void conv_kernel(const float* __restrict__ w) {
    __shared__ float s_w[688];
    __shared__ float s_in[2 * SCH];

    int tx  = threadIdx.x;               // 0..15
    int ty  = threadIdx.y;               // 0..7
    int tid = ty * 16 + tx;              // 0..127
    int w0  = blockIdx.x * 64;
    int h0  = blockIdx.y * 16;
    int b   = blockIdx.z >> 4;
    int t   = blockIdx.z & 15;

    for (int i = tid; i < 686; i += 128) s_w[i] = w[i];

    float a0[4] = {0.f, 0.f, 0.f, 0.f};
    float a1[4] = {0.f, 0.f, 0.f, 0.f};

    for (int kt = 0; kt < 7; ++kt) {
        int tin = t + kt - 3;
        if (tin < 0 || tin >= TT) continue;   // uniform per block (t uniform)

        __syncthreads();  // prior compute done before overwriting slice
        // Load slice: 2 ch x 22 rows x 70 cols, zero-padded at H/W borders
        const float* src = g_maps + ((b * 2) * TT + tin) * HWSZ;
        for (int i = tid; i < 2 * 22 * 70; i += 128) {
            int c  = i / 1540;
            int r  = i - c * 1540;
            int hh = r / 70;
            int ww = r - hh * 70;
            int gh = h0 - 3 + hh;
            int gw = w0 - 3 + ww;
            float val = 0.f;
            if ((unsigned)gh < (unsigned)HH && (unsigned)gw < (unsigned)WW)
                val = src[c * THW + gh * WW + gw];
            s_in[c * SCH + hh * SSTR + ww] = val;
        }
        __syncthreads();

#pragma unroll
        for (int c = 0; c < 2; ++c) {
            const float* basep = s_in + c * SCH + tx * 4;
            float lo[12], hi[12];
            {
                const float4* p = (const float4*)(basep + (ty * 2) * SSTR);
                float4 q0 = p[0], q1 = p[1], q2 = p[2];
                lo[0]=q0.x; lo[1]=q0.y; lo[2]=q0.z; lo[3]=q0.w;
                lo[4]=q1.x; lo[5]=q1.y; lo[6]=q1.z; lo[7]=q1.w;
                lo[8]=q2.x; lo[9]=q2.y; lo[10]=q2.z; lo[11]=q2.w;
                p = (const float4*)(basep + (ty * 2 + 1) * SSTR);
                q0 = p[0]; q1 = p[1]; q2 = p[2];
                hi[0]=q0.x; hi[1]=q0.y; hi[2]=q0.z; hi[3]=q0.w;
                hi[4]=q1.x; hi[5]=q1.y; hi[6]=q1.z; hi[7]=q1.w;
                hi[8]=q2.x; hi[9]=q2.y; hi[10]=q2.z; hi[11]=q2.w;
            }
#pragma unroll
            for (int kh = 0; kh < 7; ++kh) {
                if (kh > 0) {
#pragma unroll
                    for (int m = 0; m < 12; ++m) lo[m] = hi[m];
                    const float4* p =
                        (const float4*)(basep + (ty * 2 + kh + 1) * SSTR);
                    float4 q0 = p[0], q1 = p[1], q2 = p[2];
                    hi[0]=q0.x; hi[1]=q0.y; hi[2]=q0.z; hi[3]=q0.w;
                    hi[4]=q1.x; hi[5]=q1.y; hi[6]=q1.z; hi[7]=q1.w;
                    hi[8]=q2.x; hi[9]=q2.y; hi[10]=q2.z; hi[11]=q2.w;
                }
                const float* wp = s_w + c * 343 + kt * 49 + kh * 7;
#pragma unroll
                for (int kw = 0; kw < 7; ++kw) {
                    float wv = wp[kw];
#pragma unroll
                    for (int j = 0; j < 4; ++j) {
                        a0[j] = fmaf(wv, lo[kw + j], a0[j]);
                        a1[j] = fmaf(wv, hi[kw + j], a1[j]);
                    }
                }
            }
        }
    }

    // sigmoid + float4 store to g_attn
    int oh = h0 + ty * 2;
    float4 o0, o1;
    o0.x = 1.0f / (1.0f + __expf(-a0[0]));
    o0.y = 1.0f / (1.0f + __expf(-a0[1]));
    o0.z = 1.0f / (1.0f + __expf(-a0[2]));
    o0.w = 1.0f / (1.0f + __expf(-a0[3]));
    o1.x = 1.0f / (1.0f + __expf(-a1[0]));
    o1.y = 1.0f / (1.0f + __expf(-a1[1]));
    o1.z = 1.0f / (1.0f + __expf(-a1[2]));
    o1.w = 1.0f / (1.0f + __expf(-a1[3]));

    float4* att4 = (float4*)g_attn;
    int wq = blockIdx.x * 16 + tx;                        // w0/4 + tx
    int base = b * (THW / 4) + t * (HWSZ / 4) + oh * (WW / 4) + wq;
    att4[base]            = o0;
    att4[base + WW / 4]   = o1;
}

// ---------------------------------------------------------------------------
// Kernel 3: out = attn * x (broadcast over C). Pure streaming, float4.
// attn (4 MB total) stays L2-resident across the 64x reuse.
// ---------------------------------------------------------------------------
__global__ void mul_kernel(const float* __restrict__ x, float* __restrict__ out) {
    int idx = blockIdx.x * blockDim.x + threadIdx.x;   // float4 index
    int b  = idx >> 22;                                 // C*THW/4 = 2^22 per b
    int s4 = idx & 65535;                               // spatial f4 within ch

    float4 a = ((const float4*)g_attn)[b * 65536 + s4];
    float4 v = ((const float4*)x)[idx];
    float4 o = make_float4(v.x * a.x, v.y * a.y, v.z * a.z, v.w * a.w);
    ((float4*)out)[idx] = o;
}

// ---------------------------------------------------------------------------
extern "C" void kernel_launch(void* const* d_in, const int* in_sizes, int n_in,
                              void* d_out, int out_size) {
    const float* x = (const float*)d_in[0];   // 33554432 floats
    const float* w = (const float*)d_in[1];   // 686 floats
    float* out = (float*)d_out;

    // 1) channel max/mean: B*THW/4 = 131072 threads
    reduce_kernel<<<512, 256>>>(x);

    // 2) conv + sigmoid: tiles 64w x 16h, grid (W/64, H/16, B*T)
    dim3 cgrid(WW / 64, HH / 16, BB * TT);
    dim3 cblk(16, 8);
    conv_kernel<<<cgrid, cblk>>>(w);

    // 3) broadcast multiply: B*C*THW/4 = 8388608 threads
    mul_kernel<<<32768, 256>>>(x, out);
}

// round 11
// speedup vs baseline: 1.0249x; 1.0006x over previous
#include <cuda_runtime.h>

// Shapes: x (B=2, C=64, T=16, H=128, W=128) fp32; w (1, 2, 7, 7, 7) fp32.
// out = sigmoid(conv3d(concat(max_c(x), mean_c(x)), w, pad=3)) * x
#define CC   64
#define TT   16
#define HH   128
#define WW   128
#define HWSZ (HH * WW)           // 16384
#define THW  (TT * HWSZ)         // 262144
#define BB   2

// Scratch: maps (B,2,T,H,W) = 4 MB, attn (B,T,H,W) = 2 MB
__device__ __align__(16) float g_maps[BB * 2 * THW];
__device__ __align__(16) float g_attn[BB * THW];

// ---------------------------------------------------------------------------
// Kernel 1: channel max + mean.  One thread = one float4 spatial position,
// 64 coalesced strided float4 loads (stride 1 MB), MLP from unroll.
// ---------------------------------------------------------------------------
__global__ void reduce_kernel(const float* __restrict__ x) {
    int idx = blockIdx.x * blockDim.x + threadIdx.x;  // [0, B*THW/4)
    int b  = idx >> 16;                                // THW/4 = 65536
    int s4 = idx & 65535;

    const float4* x4 = (const float4*)x;
    int base = b * (CC * (THW / 4)) + s4;              // max 8388608, fits int

    float4 v = x4[base];
    float4 mx = v;
    float4 sm = v;
#pragma unroll 7
    for (int c = 1; c < CC; ++c) {
        float4 u = x4[base + c * (THW / 4)];
        mx.x = fmaxf(mx.x, u.x); mx.y = fmaxf(mx.y, u.y);
        mx.z = fmaxf(mx.z, u.z); mx.w = fmaxf(mx.w, u.w);
        sm.x += u.x; sm.y += u.y; sm.z += u.z; sm.w += u.w;
    }
    const float inv = 1.0f / 64.0f;
    float4 av = make_float4(sm.x * inv, sm.y * inv, sm.z * inv, sm.w * inv);

    float4* m4 = (float4*)g_maps;
    m4[(b * 2 + 0) * (THW / 4) + s4] = mx;
    m4[(b * 2 + 1) * (THW / 4) + s4] = av;
}

// ---------------------------------------------------------------------------
// Kernel 2: 7x7x7 conv over (B,2,T,H,W) maps + sigmoid -> g_attn.
// Block = (16,8) threads, output tile 64(w) x 16(h) at fixed (b,t).
// Each thread computes 4(w) x 2(h) outputs with a sliding register window
// in kh (rolling lo/hi rows), float4 LDS (conflict-free).
// Smem: weights (686 fl) + one t-slice 2ch x 22rows x stride72.
// ---------------------------------------------------------------------------
#define SSTR  72                 // smem row stride (floats), mult of 4
#define SCH   (22 * SSTR)        // per-channel smem slice (1584 floats)

__global__ void conv_kernel(const float* __restrict__ w) {
    __shared__ float s_w[688];
    __shared__ float s_in[2 * SCH];

    int tx  = threadIdx.x;               // 0..15
    int ty  = threadIdx.y;               // 0..7
    int tid = ty * 16 + tx;              // 0..127
    int w0  = blockIdx.x * 64;
    int h0  = blockIdx.y * 16;
    int b   = blockIdx.z >> 4;
    int t   = blockIdx.z & 15;

    for (int i = tid; i < 686; i += 128) s_w[i] = w[i];

    float a0[4] = {0.f, 0.f, 0.f, 0.f};
    float a1[4] = {0.f, 0.f, 0.f, 0.f};

    for (int kt = 0; kt < 7; ++kt) {
        int tin = t + kt - 3;
        if (tin < 0 || tin >= TT) continue;   // uniform per block (t uniform)

        __syncthreads();  // prior compute done before overwriting slice
        // Load slice: 2 ch x 22 rows x 70 cols, zero-padded at H/W borders
        const float* src = g_maps + ((b * 2) * TT + tin) * HWSZ;
        for (int i = tid; i < 2 * 22 * 70; i += 128) {
            int c  = i / 1540;
            int r  = i - c * 1540;
            int hh = r / 70;
            int ww = r - hh * 70;
            int gh = h0 - 3 + hh;
            int gw = w0 - 3 + ww;
            float val = 0.f;
            if ((unsigned)gh < (unsigned)HH && (unsigned)gw < (unsigned)WW)
                val = src[c * THW + gh * WW + gw];
            s_in[c * SCH + hh * SSTR + ww] = val;
        }
        __syncthreads();

#pragma unroll
        for (int c = 0; c < 2; ++c) {
            const float* basep = s_in + c * SCH + tx * 4;
            float lo[12], hi[12];
            {
                const float4* p = (const float4*)(basep + (ty * 2) * SSTR);
                float4 q0 = p[0], q1 = p[1], q2 = p[2];
                lo[0]=q0.x; lo[1]=q0.y; lo[2]=q0.z; lo[3]=q0.w;
                lo[4]=q1.x; lo[5]=q1.y; lo[6]=q1.z; lo[7]=q1.w;
                lo[8]=q2.x; lo[9]=q2.y; lo[10]=q2.z; lo[11]=q2.w;
                p = (const float4*)(basep + (ty * 2 + 1) * SSTR);
                q0 = p[0]; q1 = p[1]; q2 = p[2];
                hi[0]=q0.x; hi[1]=q0.y; hi[2]=q0.z; hi[3]=q0.w;
                hi[4]=q1.x; hi[5]=q1.y; hi[6]=q1.z; hi[7]=q1.w;
                hi[8]=q2.x; hi[9]=q2.y; hi[10]=q2.z; hi[11]=q2.w;
            }
#pragma unroll
            for (int kh = 0; kh < 7; ++kh) {
                if (kh > 0) {
#pragma unroll
                    for (int m = 0; m < 12; ++m) lo[m] = hi[m];
                    const float4* p =
                        (const float4*)(basep + (ty * 2 + kh + 1) * SSTR);
                    float4 q0 = p[0], q1 = p[1], q2 = p[2];
                    hi[0]=q0.x; hi[1]=q0.y; hi[2]=q0.z; hi[3]=q0.w;
                    hi[4]=q1.x; hi[5]=q1.y; hi[6]=q1.z; hi[7]=q1.w;
                    hi[8]=q2.x; hi[9]=q2.y; hi[10]=q2.z; hi[11]=q2.w;
                }
                const float* wp = s_w + c * 343 + kt * 49 + kh * 7;
#pragma unroll
                for (int kw = 0; kw < 7; ++kw) {
                    float wv = wp[kw];
#pragma unroll
                    for (int j = 0; j < 4; ++j) {
                        a0[j] = fmaf(wv, lo[kw + j], a0[j]);
                        a1[j] = fmaf(wv, hi[kw + j], a1[j]);
                    }
                }
            }
        }
    }

    // sigmoid + float4 store to g_attn
    int oh = h0 + ty * 2;
    float4 o0, o1;
    o0.x = 1.0f / (1.0f + __expf(-a0[0]));
    o0.y = 1.0f / (1.0f + __expf(-a0[1]));
    o0.z = 1.0f / (1.0f + __expf(-a0[2]));
    o0.w = 1.0f / (1.0f + __expf(-a0[3]));
    o1.x = 1.0f / (1.0f + __expf(-a1[0]));
    o1.y = 1.0f / (1.0f + __expf(-a1[1]));
    o1.z = 1.0f / (1.0f + __expf(-a1[2]));
    o1.w = 1.0f / (1.0f + __expf(-a1[3]));

    float4* att4 = (float4*)g_attn;
    int wq = blockIdx.x * 16 + tx;                        // w0/4 + tx
    int base = b * (THW / 4) + t * (HWSZ / 4) + oh * (WW / 4) + wq;
    att4[base]            = o0;
    att4[base + WW / 4]   = o1;
}

// ---------------------------------------------------------------------------
// Kernel 3: out = attn * x (broadcast over C). Pure streaming, float4.
// attn (4 MB total) stays L2-resident across the 64x reuse.
// ---------------------------------------------------------------------------
__global__ void mul_kernel(const float* __restrict__ x, float* __restrict__ out) {
    int idx = blockIdx.x * blockDim.x + threadIdx.x;   // float4 index
    int b  = idx >> 22;                                 // C*THW/4 = 2^22 per b
    int s4 = idx & 65535;                               // spatial f4 within ch

    float4 a = ((const float4*)g_attn)[b * 65536 + s4];
    float4 v = ((const float4*)x)[idx];
    float4 o = make_float4(v.x * a.x, v.y * a.y, v.z * a.z, v.w * a.w);
    ((float4*)out)[idx] = o;
}

// ---------------------------------------------------------------------------
extern "C" void kernel_launch(void* const* d_in, const int* in_sizes, int n_in,
                              void* d_out, int out_size) {
    const float* x = (const float*)d_in[0];   // 33554432 floats
    const float* w = (const float*)d_in[1];   // 686 floats
    float* out = (float*)d_out;

    // 1) channel max/mean: B*THW/4 = 131072 threads
    reduce_kernel<<<512, 256>>>(x);

    // 2) conv + sigmoid: tiles 64w x 16h, grid (W/64, H/16, B*T)
    dim3 cgrid(WW / 64, HH / 16, BB * TT);
    dim3 cblk(16, 8);
    conv_kernel<<<cgrid, cblk>>>(w);

    // 3) broadcast multiply: B*C*THW/4 = 8388608 threads
    mul_kernel<<<32768, 256>>>(x, out);
}